// round 10
// baseline (speedup 1.0000x reference)
#include <cuda_runtime.h>
#include <cstdint>

// ---------------- static scratch (device globals: allocation-free) ----------------
#define NMAX 100000
#define EMAX 1600000
#define HDIM 64

__device__ float g_deg[NMAX];
__device__ float g_dis[NMAX];
__device__ int   g_src[EMAX];
__device__ int   g_tgt[EMAX];
__device__ int   g_rowcnt[NMAX];
__device__ int   g_rowptr[NMAX + 1];
__device__ int   g_cursor[NMAX];
__device__ int   g_bsum[128];
__device__ int   g_bsumoff[128];
__device__ int2  g_epay[EMAX];          // {src, bits(wn)} grouped by tgt
__device__ float g_bufA[(size_t)NMAX * HDIM];
__device__ float g_bufB[(size_t)NMAX * HDIM];
__device__ float g_bufU[(size_t)NMAX * HDIM];
__device__ float g_tx1[(size_t)NMAX * HDIM];
__device__ float g_tmp[(size_t)NMAX * HDIM];
__device__ float g_weff[4 * 192 * 64];
__device__ float g_sums[64];
__device__ float g_cnt[64];

// ---------------- utility ----------------
__global__ void init_counts_kernel(int n) {
    int i = blockIdx.x * blockDim.x + threadIdx.x;
    if (i < n) { g_deg[i] = 0.f; g_rowcnt[i] = 0; }
}

__global__ void zero_pool_kernel() {
    int i = threadIdx.x;
    if (i < 64) g_sums[i] = 0.f;
    else if (i < 128) g_cnt[i - 64] = 0.f;
}

// ---------------- preprocessing ----------------
// edge_index is int32 (JAX default x64-disabled downcasts the reference's int64).
__global__ void edge_prep_kernel(const int* __restrict__ ei,
                                 const float* __restrict__ ew, int E, int N) {
    int e = blockIdx.x * blockDim.x + threadIdx.x;
    if (e >= E) return;
    int s = ei[e];
    int t = ei[(size_t)E + e];
    if ((unsigned)s >= (unsigned)N) s = 0;   // harden against dtype surprises
    if ((unsigned)t >= (unsigned)N) t = 0;
    g_src[e] = s;
    g_tgt[e] = t;
    atomicAdd(&g_deg[s], ew[e]);
    atomicAdd(&g_rowcnt[t], 1);
}

// ---- multi-block exclusive scan of g_rowcnt -> g_rowptr (+ dis fused) ----
__global__ void scan_block_kernel(int N) {
    __shared__ int wsum[32];
    int tid = threadIdx.x, lane = tid & 31, wid = tid >> 5;
    int i = blockIdx.x * 1024 + tid;
    // fused: dis = rsqrt(deg)
    if (i < N) {
        float d = g_deg[i];
        g_dis[i] = (d > 0.f) ? rsqrtf(d) : 0.f;
    }
    int v = (i < N) ? g_rowcnt[i] : 0;
    int s = v;
#pragma unroll
    for (int o = 1; o < 32; o <<= 1) {
        int u = __shfl_up_sync(0xffffffffu, s, o);
        if (lane >= o) s += u;
    }
    if (lane == 31) wsum[wid] = s;
    __syncthreads();
    if (tid < 32) {
        int s2 = wsum[tid];
#pragma unroll
        for (int o = 1; o < 32; o <<= 1) {
            int u = __shfl_up_sync(0xffffffffu, s2, o);
            if (tid >= o) s2 += u;
        }
        wsum[tid] = s2;
    }
    __syncthreads();
    int excl = (wid ? wsum[wid - 1] : 0) + (s - v);
    if (i < N) g_rowptr[i] = excl;           // block-local exclusive
    if (tid == 1023) g_bsum[blockIdx.x] = wsum[31];
}

__global__ void scan_bsum_kernel(int nb) {   // 1 block, 128 threads, nb <= 128
    __shared__ int ws[4];
    int tid = threadIdx.x, lane = tid & 31, wid = tid >> 5;
    int v = (tid < nb) ? g_bsum[tid] : 0;
    int s = v;
#pragma unroll
    for (int o = 1; o < 32; o <<= 1) {
        int u = __shfl_up_sync(0xffffffffu, s, o);
        if (lane >= o) s += u;
    }
    if (lane == 31) ws[wid] = s;
    __syncthreads();
    if (tid == 0) { int a = 0; for (int w = 0; w < 4; w++) { int t = ws[w]; ws[w] = a; a += t; } }
    __syncthreads();
    int excl = ws[wid] + (s - v);
    if (tid < nb) g_bsumoff[tid] = excl;
}

__global__ void scan_add_kernel(int N, int E) {
    int i = blockIdx.x * 1024 + threadIdx.x;
    if (i < N) {
        int r = g_rowptr[i] + g_bsumoff[blockIdx.x];
        g_rowptr[i] = r;
        g_cursor[i] = r;
    }
    if (blockIdx.x == 0 && threadIdx.x == 0) g_rowptr[N] = E;
}

// scatter edges into CSR slots; fuse wn computation
__global__ void fill_kernel(const float* __restrict__ ew, int E) {
    int e = blockIdx.x * blockDim.x + threadIdx.x;
    if (e >= E) return;
    int s = g_src[e];
    int t = g_tgt[e];
    float wn = -g_dis[s] * ew[e] * g_dis[t];
    int pos = atomicAdd(&g_cursor[t], 1);
    g_epay[pos] = make_int2(s, __float_as_int(wn));
}

// Weff[l][kk][o]: kk<64 -> W0-W2 ; 64..127 -> W1 ; 128..191 -> 2*W2
__global__ void weff_kernel(const float* __restrict__ w) {
    int idx = blockIdx.x * blockDim.x + threadIdx.x;
    if (idx >= 4 * 192 * 64) return;
    int o  = idx & 63;
    int kk = (idx >> 6) % 192;
    int l  = idx / (192 * 64);
    const float* wl = w + (size_t)l * 3 * 4096;
    float v;
    if (kk < 64)       v = wl[kk * 64 + o] - wl[2 * 4096 + kk * 64 + o];
    else if (kk < 128) v = wl[4096 + (kk - 64) * 64 + o];
    else               v = 2.f * wl[2 * 4096 + (kk - 128) * 64 + o];
    g_weff[idx] = v;
}

// ================= fused block-role kernel =================
// 1-in-17 blocks: K=64 GEMM tile (BM=128, BN=64): u (+)= A @ W [+ bias]
// 16-in-17 blocks: warp-per-node prop: pout = P(h)
// GEMM FFMA rides under the prop's memory stalls.
__device__ __forceinline__ void gemm64_core(const float* __restrict__ A,
                                            const float* __restrict__ W,
                                            const float* __restrict__ bias,
                                            const float* __restrict__ uin,
                                            float* __restrict__ uout,
                                            int m0, int N) {
    __shared__ float As[16][128];
    __shared__ float Bs[16][64];
    int tid = threadIdx.x;
    int tm = tid >> 4;          // 0..15 (8 rows each)
    int tn = tid & 15;          // 0..15 (4 cols each)
    float acc[8][4];
#pragma unroll
    for (int i = 0; i < 8; i++)
#pragma unroll
        for (int j = 0; j < 4; j++) acc[i][j] = 0.f;

    int lrow = tid >> 1;
    int kk = (tid & 1) << 3;
    int grow = m0 + lrow;
    bool a_ok = (grow < N);

#pragma unroll
    for (int kt = 0; kt < 4; kt++) {
        int k0 = kt << 4;
        float4 a0 = make_float4(0.f, 0.f, 0.f, 0.f);
        float4 a1 = make_float4(0.f, 0.f, 0.f, 0.f);
        if (a_ok) {
            const float* rp = A + (size_t)grow * 64 + k0 + kk;
            a0 = *reinterpret_cast<const float4*>(rp);
            a1 = *reinterpret_cast<const float4*>(rp + 4);
        }
        As[kk + 0][lrow] = a0.x; As[kk + 1][lrow] = a0.y;
        As[kk + 2][lrow] = a0.z; As[kk + 3][lrow] = a0.w;
        As[kk + 4][lrow] = a1.x; As[kk + 5][lrow] = a1.y;
        As[kk + 6][lrow] = a1.z; As[kk + 7][lrow] = a1.w;
        {
            int kr = tid >> 4;
            int c4 = (tid & 15) << 2;
            float4 bv = *reinterpret_cast<const float4*>(W + (size_t)(k0 + kr) * 64 + c4);
            *reinterpret_cast<float4*>(&Bs[kr][c4]) = bv;
        }
        __syncthreads();
#pragma unroll
        for (int k = 0; k < 16; k++) {
            float4 b = *reinterpret_cast<const float4*>(&Bs[k][tn << 2]);
            float4 x0 = *reinterpret_cast<const float4*>(&As[k][tm << 3]);
            float4 x1 = *reinterpret_cast<const float4*>(&As[k][(tm << 3) + 4]);
            float av[8] = {x0.x, x0.y, x0.z, x0.w, x1.x, x1.y, x1.z, x1.w};
#pragma unroll
            for (int i = 0; i < 8; i++) {
                acc[i][0] += av[i] * b.x;
                acc[i][1] += av[i] * b.y;
                acc[i][2] += av[i] * b.z;
                acc[i][3] += av[i] * b.w;
            }
        }
        __syncthreads();
    }
    float4 bb = make_float4(0.f, 0.f, 0.f, 0.f);
    if (bias) bb = *reinterpret_cast<const float4*>(bias + (tn << 2));
#pragma unroll
    for (int i = 0; i < 8; i++) {
        int rowg = m0 + (tm << 3) + i;
        if (rowg < N) {
            float4 o;
            o.x = acc[i][0] + bb.x;
            o.y = acc[i][1] + bb.y;
            o.z = acc[i][2] + bb.z;
            o.w = acc[i][3] + bb.w;
            const float* uip = uin ? (uin + (size_t)rowg * 64 + (tn << 2)) : nullptr;
            if (uip) {
                float4 p = *reinterpret_cast<const float4*>(uip);
                o.x += p.x; o.y += p.y; o.z += p.z; o.w += p.w;
            }
            *reinterpret_cast<float4*>(uout + (size_t)rowg * 64 + (tn << 2)) = o;
        }
    }
}

__device__ __forceinline__ void prop_core(const float* __restrict__ h,
                                          float* __restrict__ pout,
                                          int node) {
    int lane = threadIdx.x & 31;
    int beg = g_rowptr[node];
    int end = g_rowptr[node + 1];
    const float2* __restrict__ hp = reinterpret_cast<const float2*>(h);
    float ax = 0.f, ay = 0.f;
    int j = beg;
    for (; j + 4 <= end; j += 4) {
        int2 p0 = g_epay[j];
        int2 p1 = g_epay[j + 1];
        int2 p2 = g_epay[j + 2];
        int2 p3 = g_epay[j + 3];
        float2 v0 = hp[(size_t)p0.x * 32 + lane];
        float2 v1 = hp[(size_t)p1.x * 32 + lane];
        float2 v2 = hp[(size_t)p2.x * 32 + lane];
        float2 v3 = hp[(size_t)p3.x * 32 + lane];
        float w0 = __int_as_float(p0.y), w1 = __int_as_float(p1.y);
        float w2 = __int_as_float(p2.y), w3 = __int_as_float(p3.y);
        ax += w0 * v0.x; ay += w0 * v0.y;
        ax += w1 * v1.x; ay += w1 * v1.y;
        ax += w2 * v2.x; ay += w2 * v2.y;
        ax += w3 * v3.x; ay += w3 * v3.y;
    }
    for (; j < end; j++) {
        int2 p = g_epay[j];
        float w = __int_as_float(p.y);
        float2 v = hp[(size_t)p.x * 32 + lane];
        ax += w * v.x; ay += w * v.y;
    }
    reinterpret_cast<float2*>(pout)[(size_t)node * 32 + lane] = make_float2(ax, ay);
}

__global__ void __launch_bounds__(256, 4)
fused_prop_gemm_kernel(const float* __restrict__ h, float* __restrict__ pout,
                       const float* __restrict__ A, const float* __restrict__ W,
                       const float* __restrict__ bias, const float* __restrict__ uin,
                       float* __restrict__ uout, int N) {
    int g = blockIdx.x / 17;
    int r = blockIdx.x - g * 17;
    if (r == 16) {
        int m0 = g * 128;
        if (m0 < N) gemm64_core(A, W, bias, uin, uout, m0, N);
    } else {
        int pb = g * 16 + r;
        int node = pb * 8 + (threadIdx.x >> 5);
        if (node < N) prop_core(h, pout, node);
    }
}

// standalone K=64 GEMM with add-input (the exposed tail per layer)
__global__ void __launch_bounds__(256, 4)
gemm64_kernel(const float* __restrict__ A, const float* __restrict__ W,
              const float* __restrict__ uin, float* __restrict__ out, int N) {
    gemm64_core(A, W, nullptr, uin, out, blockIdx.x * 128, N);
}

// ---------------- readout MLP (64->32 relu ->1) + scatter mean ----------------
__global__ void readout_kernel(const float* __restrict__ y, const int* __restrict__ batch,
                               const float* __restrict__ wr1, const float* __restrict__ br1,
                               const float* __restrict__ wr2, const float* __restrict__ br2,
                               int n, int G) {
    __shared__ float Wsm[64 * 32];
    __shared__ float w2sm[32];
    __shared__ float b1sm[32];
    for (int i = threadIdx.x; i < 64 * 32; i += blockDim.x) Wsm[i] = wr1[i];
    if (threadIdx.x < 32) {
        w2sm[threadIdx.x] = wr2[threadIdx.x];
        b1sm[threadIdx.x] = br1[threadIdx.x];
    }
    __syncthreads();
    float b2 = br2[0];
    int lane = threadIdx.x & 31;
    int warp = (blockIdx.x * blockDim.x + threadIdx.x) >> 5;
    int nwarps = (gridDim.x * blockDim.x) >> 5;
    for (int node = warp; node < n; node += nwarps) {
        float yv0 = y[(size_t)node * 64 + lane];
        float yv1 = y[(size_t)node * 64 + 32 + lane];
        float acc = b1sm[lane];
#pragma unroll
        for (int k = 0; k < 32; k++)
            acc += __shfl_sync(0xffffffffu, yv0, k) * Wsm[k * 32 + lane];
#pragma unroll
        for (int k = 0; k < 32; k++)
            acc += __shfl_sync(0xffffffffu, yv1, k) * Wsm[(32 + k) * 32 + lane];
        acc = fmaxf(acc, 0.f);
        float r = acc * w2sm[lane];
#pragma unroll
        for (int off = 16; off; off >>= 1)
            r += __shfl_xor_sync(0xffffffffu, r, off);
        if (lane == 0) {
            int g = batch[node];
            if ((unsigned)g < (unsigned)G) {
                atomicAdd(&g_sums[g], r + b2);
                atomicAdd(&g_cnt[g], 1.f);
            }
        }
    }
}

__global__ void finalize_kernel(float* __restrict__ out, int G) {
    int g = threadIdx.x;
    if (g < G) out[g] = g_sums[g] / fmaxf(g_cnt[g], 1.f);
}

// ---------------- host ----------------
extern "C" void kernel_launch(void* const* d_in, const int* in_sizes, int n_in,
                              void* d_out, int out_size) {
    const float* x        = (const float*)d_in[0];
    const int*   ei       = (const int*)d_in[1];     // int32 (JAX x64 disabled)
    const float* ew       = (const float*)d_in[2];
    const int*   batch    = (const int*)d_in[3];     // int32
    const float* w_layers = (const float*)d_in[4];
    const float* b_layers = (const float*)d_in[5];
    const float* wr1      = (const float*)d_in[6];
    const float* br1      = (const float*)d_in[7];
    const float* wr2      = (const float*)d_in[8];
    const float* br2      = (const float*)d_in[9];

    int N = in_sizes[0] / HDIM;
    int E = in_sizes[1] / 2;
    int G = out_size;

    float *bufA, *bufB, *bufU, *tx1, *tmp, *weff;
    cudaGetSymbolAddress((void**)&bufA, g_bufA);
    cudaGetSymbolAddress((void**)&bufB, g_bufB);
    cudaGetSymbolAddress((void**)&bufU, g_bufU);
    cudaGetSymbolAddress((void**)&tx1,  g_tx1);
    cudaGetSymbolAddress((void**)&tmp,  g_tmp);
    cudaGetSymbolAddress((void**)&weff, g_weff);

    const int TPB = 256;
    int nb = (N + 1023) / 1024;          // scan blocks (<=128)

    // preprocessing: degrees + CSR by target
    init_counts_kernel<<<(N + TPB - 1) / TPB, TPB>>>(N);
    edge_prep_kernel<<<(E + TPB - 1) / TPB, TPB>>>(ei, ew, E, N);
    scan_block_kernel<<<nb, 1024>>>(N);
    scan_bsum_kernel<<<1, 128>>>(nb);
    scan_add_kernel<<<nb, 1024>>>(N, E);
    fill_kernel<<<(E + TPB - 1) / TPB, TPB>>>(ew, E);
    weff_kernel<<<(4 * 192 * 64 + TPB - 1) / TPB, TPB>>>(w_layers);

    // fused grid: NG groups of 17 blocks (16 prop + 1 gemm)
    int ng_gemm = (N + 127) / 128;
    int ng_prop = (((N + 7) / 8) + 15) / 16;
    int NG = ng_gemm > ng_prop ? ng_gemm : ng_prop;
    int fgrid = NG * 17;
    int ggrid = (N + 127) / 128;

    const float* ycur = x;
    float* bufs[2] = {bufA, bufB};
    for (int l = 0; l < 4; l++) {
        const float* wl = weff + (size_t)l * 192 * 64;
        const float* bl = b_layers + (size_t)l * 64;
        // step1: tx1 = P(y)   ||  u = y @ (W0-W2) + b
        fused_prop_gemm_kernel<<<fgrid, TPB>>>(ycur, tx1, ycur, wl, bl, nullptr, bufU, N);
        // step2: tmp = P(tx1) ||  u += tx1 @ W1
        fused_prop_gemm_kernel<<<fgrid, TPB>>>(tx1, tmp, tx1, wl + 64 * 64, nullptr, bufU, bufU, N);
        // step3: y' = u + tmp @ (2W2)
        gemm64_kernel<<<ggrid, TPB>>>(tmp, wl + 128 * 64, bufU, bufs[l & 1], N);
        ycur = bufs[l & 1];
    }

    // readout + pooling
    zero_pool_kernel<<<1, 128>>>();
    readout_kernel<<<256, TPB>>>(ycur, batch, wr1, br1, wr2, br2, N, G);
    finalize_kernel<<<1, 64>>>((float*)d_out, G);
}

// round 11
// speedup vs baseline: 1.0036x; 1.0036x over previous
#include <cuda_runtime.h>
#include <cstdint>

// ---------------- static scratch (device globals: allocation-free) ----------------
#define NMAX 100000
#define EMAX 1600000
#define HDIM 64

__device__ float g_deg[NMAX];
__device__ float g_dis[NMAX];
__device__ int   g_src[EMAX];
__device__ int   g_tgt[EMAX];
__device__ int   g_rowcnt[NMAX];
__device__ int   g_rowptr[NMAX + 1];
__device__ int   g_cursor[NMAX];
__device__ int   g_bsum[128];
__device__ int   g_bsumoff[128];
__device__ int2  g_epay[EMAX];          // {src, bits(wn)} grouped by tgt
__device__ float g_bufA[(size_t)NMAX * HDIM];
__device__ float g_bufB[(size_t)NMAX * HDIM];
__device__ float g_bufU[(size_t)NMAX * HDIM];
__device__ float g_tx1[(size_t)NMAX * HDIM];
__device__ float g_tmp[(size_t)NMAX * HDIM];
__device__ float g_weff[4 * 192 * 64];
__device__ float g_sums[64];
__device__ float g_cnt[64];

// ---------------- utility ----------------
__global__ void init_counts_kernel(int n) {
    int i = blockIdx.x * blockDim.x + threadIdx.x;
    if (i < n) { g_deg[i] = 0.f; g_rowcnt[i] = 0; }
}

__global__ void zero_pool_kernel() {
    int i = threadIdx.x;
    if (i < 64) g_sums[i] = 0.f;
    else if (i < 128) g_cnt[i - 64] = 0.f;
}

// ---------------- preprocessing ----------------
// edge_index is int32 (JAX default x64-disabled downcasts the reference's int64).
__global__ void edge_prep_kernel(const int* __restrict__ ei,
                                 const float* __restrict__ ew, int E, int N) {
    int e = blockIdx.x * blockDim.x + threadIdx.x;
    if (e >= E) return;
    int s = ei[e];
    int t = ei[(size_t)E + e];
    if ((unsigned)s >= (unsigned)N) s = 0;   // harden against dtype surprises
    if ((unsigned)t >= (unsigned)N) t = 0;
    g_src[e] = s;
    g_tgt[e] = t;
    atomicAdd(&g_deg[s], ew[e]);
    atomicAdd(&g_rowcnt[t], 1);
}

// ---- multi-block exclusive scan of g_rowcnt -> g_rowptr (+ dis fused) ----
__global__ void scan_block_kernel(int N) {
    __shared__ int wsum[32];
    int tid = threadIdx.x, lane = tid & 31, wid = tid >> 5;
    int i = blockIdx.x * 1024 + tid;
    // fused: dis = rsqrt(deg)
    if (i < N) {
        float d = g_deg[i];
        g_dis[i] = (d > 0.f) ? rsqrtf(d) : 0.f;
    }
    int v = (i < N) ? g_rowcnt[i] : 0;
    int s = v;
#pragma unroll
    for (int o = 1; o < 32; o <<= 1) {
        int u = __shfl_up_sync(0xffffffffu, s, o);
        if (lane >= o) s += u;
    }
    if (lane == 31) wsum[wid] = s;
    __syncthreads();
    if (tid < 32) {
        int s2 = wsum[tid];
#pragma unroll
        for (int o = 1; o < 32; o <<= 1) {
            int u = __shfl_up_sync(0xffffffffu, s2, o);
            if (tid >= o) s2 += u;
        }
        wsum[tid] = s2;
    }
    __syncthreads();
    int excl = (wid ? wsum[wid - 1] : 0) + (s - v);
    if (i < N) g_rowptr[i] = excl;           // block-local exclusive
    if (tid == 1023) g_bsum[blockIdx.x] = wsum[31];
}

__global__ void scan_bsum_kernel(int nb) {   // 1 block, 128 threads, nb <= 128
    __shared__ int ws[4];
    int tid = threadIdx.x, lane = tid & 31, wid = tid >> 5;
    int v = (tid < nb) ? g_bsum[tid] : 0;
    int s = v;
#pragma unroll
    for (int o = 1; o < 32; o <<= 1) {
        int u = __shfl_up_sync(0xffffffffu, s, o);
        if (lane >= o) s += u;
    }
    if (lane == 31) ws[wid] = s;
    __syncthreads();
    if (tid == 0) { int a = 0; for (int w = 0; w < 4; w++) { int t = ws[w]; ws[w] = a; a += t; } }
    __syncthreads();
    int excl = ws[wid] + (s - v);
    if (tid < nb) g_bsumoff[tid] = excl;
}

__global__ void scan_add_kernel(int N, int E) {
    int i = blockIdx.x * 1024 + threadIdx.x;
    if (i < N) {
        int r = g_rowptr[i] + g_bsumoff[blockIdx.x];
        g_rowptr[i] = r;
        g_cursor[i] = r;
    }
    if (blockIdx.x == 0 && threadIdx.x == 0) g_rowptr[N] = E;
}

// scatter edges into CSR slots; fuse wn computation
__global__ void fill_kernel(const float* __restrict__ ew, int E) {
    int e = blockIdx.x * blockDim.x + threadIdx.x;
    if (e >= E) return;
    int s = g_src[e];
    int t = g_tgt[e];
    float wn = -g_dis[s] * ew[e] * g_dis[t];
    int pos = atomicAdd(&g_cursor[t], 1);
    g_epay[pos] = make_int2(s, __float_as_int(wn));
}

// Weff[l][kk][o]: kk<64 -> W0-W2 ; 64..127 -> W1 ; 128..191 -> 2*W2
__global__ void weff_kernel(const float* __restrict__ w) {
    int idx = blockIdx.x * blockDim.x + threadIdx.x;
    if (idx >= 4 * 192 * 64) return;
    int o  = idx & 63;
    int kk = (idx >> 6) % 192;
    int l  = idx / (192 * 64);
    const float* wl = w + (size_t)l * 3 * 4096;
    float v;
    if (kk < 64)       v = wl[kk * 64 + o] - wl[2 * 4096 + kk * 64 + o];
    else if (kk < 128) v = wl[4096 + (kk - 64) * 64 + o];
    else               v = 2.f * wl[2 * 4096 + (kk - 128) * 64 + o];
    g_weff[idx] = v;
}

// ================= fused block-role kernel =================
// 1-in-17 blocks: K=64 GEMM tile (BM=128, BN=64): u (+)= A @ W [+ bias]
// 16-in-17 blocks: warp-per-node prop: pout = P(h)
// GEMM FFMA rides under the prop's memory stalls.
__device__ __forceinline__ void gemm64_core(const float* __restrict__ A,
                                            const float* __restrict__ W,
                                            const float* __restrict__ bias,
                                            const float* __restrict__ uin,
                                            float* __restrict__ uout,
                                            int m0, int N) {
    __shared__ float As[16][128];
    __shared__ float Bs[16][64];
    int tid = threadIdx.x;
    int tm = tid >> 4;          // 0..15 (8 rows each)
    int tn = tid & 15;          // 0..15 (4 cols each)
    float acc[8][4];
#pragma unroll
    for (int i = 0; i < 8; i++)
#pragma unroll
        for (int j = 0; j < 4; j++) acc[i][j] = 0.f;

    int lrow = tid >> 1;
    int kk = (tid & 1) << 3;
    int grow = m0 + lrow;
    bool a_ok = (grow < N);

#pragma unroll
    for (int kt = 0; kt < 4; kt++) {
        int k0 = kt << 4;
        float4 a0 = make_float4(0.f, 0.f, 0.f, 0.f);
        float4 a1 = make_float4(0.f, 0.f, 0.f, 0.f);
        if (a_ok) {
            const float* rp = A + (size_t)grow * 64 + k0 + kk;
            a0 = *reinterpret_cast<const float4*>(rp);
            a1 = *reinterpret_cast<const float4*>(rp + 4);
        }
        As[kk + 0][lrow] = a0.x; As[kk + 1][lrow] = a0.y;
        As[kk + 2][lrow] = a0.z; As[kk + 3][lrow] = a0.w;
        As[kk + 4][lrow] = a1.x; As[kk + 5][lrow] = a1.y;
        As[kk + 6][lrow] = a1.z; As[kk + 7][lrow] = a1.w;
        {
            int kr = tid >> 4;
            int c4 = (tid & 15) << 2;
            float4 bv = *reinterpret_cast<const float4*>(W + (size_t)(k0 + kr) * 64 + c4);
            *reinterpret_cast<float4*>(&Bs[kr][c4]) = bv;
        }
        __syncthreads();
#pragma unroll
        for (int k = 0; k < 16; k++) {
            float4 b = *reinterpret_cast<const float4*>(&Bs[k][tn << 2]);
            float4 x0 = *reinterpret_cast<const float4*>(&As[k][tm << 3]);
            float4 x1 = *reinterpret_cast<const float4*>(&As[k][(tm << 3) + 4]);
            float av[8] = {x0.x, x0.y, x0.z, x0.w, x1.x, x1.y, x1.z, x1.w};
#pragma unroll
            for (int i = 0; i < 8; i++) {
                acc[i][0] += av[i] * b.x;
                acc[i][1] += av[i] * b.y;
                acc[i][2] += av[i] * b.z;
                acc[i][3] += av[i] * b.w;
            }
        }
        __syncthreads();
    }
    float4 bb = make_float4(0.f, 0.f, 0.f, 0.f);
    if (bias) bb = *reinterpret_cast<const float4*>(bias + (tn << 2));
#pragma unroll
    for (int i = 0; i < 8; i++) {
        int rowg = m0 + (tm << 3) + i;
        if (rowg < N) {
            float4 o;
            o.x = acc[i][0] + bb.x;
            o.y = acc[i][1] + bb.y;
            o.z = acc[i][2] + bb.z;
            o.w = acc[i][3] + bb.w;
            const float* uip = uin ? (uin + (size_t)rowg * 64 + (tn << 2)) : nullptr;
            if (uip) {
                float4 p = *reinterpret_cast<const float4*>(uip);
                o.x += p.x; o.y += p.y; o.z += p.z; o.w += p.w;
            }
            *reinterpret_cast<float4*>(uout + (size_t)rowg * 64 + (tn << 2)) = o;
        }
    }
}

__device__ __forceinline__ void prop_core(const float* __restrict__ h,
                                          float* __restrict__ pout,
                                          int node) {
    int lane = threadIdx.x & 31;
    int beg = g_rowptr[node];
    int end = g_rowptr[node + 1];
    const float2* __restrict__ hp = reinterpret_cast<const float2*>(h);
    float ax = 0.f, ay = 0.f;
    int j = beg;
    for (; j + 4 <= end; j += 4) {
        int2 p0 = g_epay[j];
        int2 p1 = g_epay[j + 1];
        int2 p2 = g_epay[j + 2];
        int2 p3 = g_epay[j + 3];
        float2 v0 = hp[(size_t)p0.x * 32 + lane];
        float2 v1 = hp[(size_t)p1.x * 32 + lane];
        float2 v2 = hp[(size_t)p2.x * 32 + lane];
        float2 v3 = hp[(size_t)p3.x * 32 + lane];
        float w0 = __int_as_float(p0.y), w1 = __int_as_float(p1.y);
        float w2 = __int_as_float(p2.y), w3 = __int_as_float(p3.y);
        ax += w0 * v0.x; ay += w0 * v0.y;
        ax += w1 * v1.x; ay += w1 * v1.y;
        ax += w2 * v2.x; ay += w2 * v2.y;
        ax += w3 * v3.x; ay += w3 * v3.y;
    }
    for (; j < end; j++) {
        int2 p = g_epay[j];
        float w = __int_as_float(p.y);
        float2 v = hp[(size_t)p.x * 32 + lane];
        ax += w * v.x; ay += w * v.y;
    }
    reinterpret_cast<float2*>(pout)[(size_t)node * 32 + lane] = make_float2(ax, ay);
}

__global__ void __launch_bounds__(256, 4)
fused_prop_gemm_kernel(const float* __restrict__ h, float* __restrict__ pout,
                       const float* __restrict__ A, const float* __restrict__ W,
                       const float* __restrict__ bias, const float* __restrict__ uin,
                       float* __restrict__ uout, int N) {
    int g = blockIdx.x / 17;
    int r = blockIdx.x - g * 17;
    if (r == 16) {
        int m0 = g * 128;
        if (m0 < N) gemm64_core(A, W, bias, uin, uout, m0, N);
    } else {
        int pb = g * 16 + r;
        int node = pb * 8 + (threadIdx.x >> 5);
        if (node < N) prop_core(h, pout, node);
    }
}

// standalone K=64 GEMM with add-input (the exposed tail per layer)
__global__ void __launch_bounds__(256, 4)
gemm64_kernel(const float* __restrict__ A, const float* __restrict__ W,
              const float* __restrict__ uin, float* __restrict__ out, int N) {
    gemm64_core(A, W, nullptr, uin, out, blockIdx.x * 128, N);
}

// ---------------- readout MLP (64->32 relu ->1) + scatter mean ----------------
__global__ void readout_kernel(const float* __restrict__ y, const int* __restrict__ batch,
                               const float* __restrict__ wr1, const float* __restrict__ br1,
                               const float* __restrict__ wr2, const float* __restrict__ br2,
                               int n, int G) {
    __shared__ float Wsm[64 * 32];
    __shared__ float w2sm[32];
    __shared__ float b1sm[32];
    for (int i = threadIdx.x; i < 64 * 32; i += blockDim.x) Wsm[i] = wr1[i];
    if (threadIdx.x < 32) {
        w2sm[threadIdx.x] = wr2[threadIdx.x];
        b1sm[threadIdx.x] = br1[threadIdx.x];
    }
    __syncthreads();
    float b2 = br2[0];
    int lane = threadIdx.x & 31;
    int warp = (blockIdx.x * blockDim.x + threadIdx.x) >> 5;
    int nwarps = (gridDim.x * blockDim.x) >> 5;
    for (int node = warp; node < n; node += nwarps) {
        float yv0 = y[(size_t)node * 64 + lane];
        float yv1 = y[(size_t)node * 64 + 32 + lane];
        float acc = b1sm[lane];
#pragma unroll
        for (int k = 0; k < 32; k++)
            acc += __shfl_sync(0xffffffffu, yv0, k) * Wsm[k * 32 + lane];
#pragma unroll
        for (int k = 0; k < 32; k++)
            acc += __shfl_sync(0xffffffffu, yv1, k) * Wsm[(32 + k) * 32 + lane];
        acc = fmaxf(acc, 0.f);
        float r = acc * w2sm[lane];
#pragma unroll
        for (int off = 16; off; off >>= 1)
            r += __shfl_xor_sync(0xffffffffu, r, off);
        if (lane == 0) {
            int g = batch[node];
            if ((unsigned)g < (unsigned)G) {
                atomicAdd(&g_sums[g], r + b2);
                atomicAdd(&g_cnt[g], 1.f);
            }
        }
    }
}

__global__ void finalize_kernel(float* __restrict__ out, int G) {
    int g = threadIdx.x;
    if (g < G) out[g] = g_sums[g] / fmaxf(g_cnt[g], 1.f);
}

// ---------------- host ----------------
extern "C" void kernel_launch(void* const* d_in, const int* in_sizes, int n_in,
                              void* d_out, int out_size) {
    const float* x        = (const float*)d_in[0];
    const int*   ei       = (const int*)d_in[1];     // int32 (JAX x64 disabled)
    const float* ew       = (const float*)d_in[2];
    const int*   batch    = (const int*)d_in[3];     // int32
    const float* w_layers = (const float*)d_in[4];
    const float* b_layers = (const float*)d_in[5];
    const float* wr1      = (const float*)d_in[6];
    const float* br1      = (const float*)d_in[7];
    const float* wr2      = (const float*)d_in[8];
    const float* br2      = (const float*)d_in[9];

    int N = in_sizes[0] / HDIM;
    int E = in_sizes[1] / 2;
    int G = out_size;

    float *bufA, *bufB, *bufU, *tx1, *tmp, *weff;
    cudaGetSymbolAddress((void**)&bufA, g_bufA);
    cudaGetSymbolAddress((void**)&bufB, g_bufB);
    cudaGetSymbolAddress((void**)&bufU, g_bufU);
    cudaGetSymbolAddress((void**)&tx1,  g_tx1);
    cudaGetSymbolAddress((void**)&tmp,  g_tmp);
    cudaGetSymbolAddress((void**)&weff, g_weff);

    const int TPB = 256;
    int nb = (N + 1023) / 1024;          // scan blocks (<=128)

    // preprocessing: degrees + CSR by target
    init_counts_kernel<<<(N + TPB - 1) / TPB, TPB>>>(N);
    edge_prep_kernel<<<(E + TPB - 1) / TPB, TPB>>>(ei, ew, E, N);
    scan_block_kernel<<<nb, 1024>>>(N);
    scan_bsum_kernel<<<1, 128>>>(nb);
    scan_add_kernel<<<nb, 1024>>>(N, E);
    fill_kernel<<<(E + TPB - 1) / TPB, TPB>>>(ew, E);
    weff_kernel<<<(4 * 192 * 64 + TPB - 1) / TPB, TPB>>>(w_layers);

    // fused grid: NG groups of 17 blocks (16 prop + 1 gemm)
    int ng_gemm = (N + 127) / 128;
    int ng_prop = (((N + 7) / 8) + 15) / 16;
    int NG = ng_gemm > ng_prop ? ng_gemm : ng_prop;
    int fgrid = NG * 17;
    int ggrid = (N + 127) / 128;

    const float* ycur = x;
    float* bufs[2] = {bufA, bufB};
    for (int l = 0; l < 4; l++) {
        const float* wl = weff + (size_t)l * 192 * 64;
        const float* bl = b_layers + (size_t)l * 64;
        // step1: tx1 = P(y)   ||  u = y @ (W0-W2) + b
        fused_prop_gemm_kernel<<<fgrid, TPB>>>(ycur, tx1, ycur, wl, bl, nullptr, bufU, N);
        // step2: tmp = P(tx1) ||  u += tx1 @ W1
        fused_prop_gemm_kernel<<<fgrid, TPB>>>(tx1, tmp, tx1, wl + 64 * 64, nullptr, bufU, bufU, N);
        // step3: y' = u + tmp @ (2W2)
        gemm64_kernel<<<ggrid, TPB>>>(tmp, wl + 128 * 64, bufU, bufs[l & 1], N);
        ycur = bufs[l & 1];
    }

    // readout + pooling
    zero_pool_kernel<<<1, 128>>>();
    readout_kernel<<<256, TPB>>>(ycur, batch, wr1, br1, wr2, br2, N, G);
    finalize_kernel<<<1, 64>>>((float*)d_out, G);
}

// round 12
// speedup vs baseline: 1.3167x; 1.3120x over previous
#include <cuda_runtime.h>
#include <cstdint>

// ---------------- static scratch (device globals: allocation-free) ----------------
#define NMAX 100000
#define EMAX 1600000
#define HDIM 64

__device__ float g_deg[NMAX];
__device__ float g_dis[NMAX];
__device__ int   g_src[EMAX];
__device__ int   g_tgt[EMAX];
__device__ int   g_rowcnt[NMAX];
__device__ int   g_rowptr[NMAX + 1];
__device__ int   g_cursor[NMAX];
__device__ int   g_bsum[128];
__device__ int   g_bsumoff[128];
__device__ int2  g_epay[EMAX];          // {src, bits(wn)} grouped by tgt
__device__ float g_bufA[(size_t)NMAX * HDIM];
__device__ float g_bufB[(size_t)NMAX * HDIM];
__device__ float g_tx1[(size_t)NMAX * HDIM];
__device__ float g_tmp[(size_t)NMAX * HDIM];
__device__ float g_weff[4 * 192 * 64];
__device__ float g_sums[64];
__device__ float g_cnt[64];

// ---------------- utility ----------------
__global__ void init_counts_kernel(int n) {
    int i = blockIdx.x * blockDim.x + threadIdx.x;
    if (i < n) { g_deg[i] = 0.f; g_rowcnt[i] = 0; }
}

__global__ void zero_pool_kernel() {
    int i = threadIdx.x;
    if (i < 64) g_sums[i] = 0.f;
    else if (i < 128) g_cnt[i - 64] = 0.f;
}

// ---------------- preprocessing ----------------
__global__ void edge_prep_kernel(const int* __restrict__ ei,
                                 const float* __restrict__ ew, int E, int N) {
    int e = blockIdx.x * blockDim.x + threadIdx.x;
    if (e >= E) return;
    int s = ei[e];
    int t = ei[(size_t)E + e];
    if ((unsigned)s >= (unsigned)N) s = 0;
    if ((unsigned)t >= (unsigned)N) t = 0;
    g_src[e] = s;
    g_tgt[e] = t;
    atomicAdd(&g_deg[s], ew[e]);
    atomicAdd(&g_rowcnt[t], 1);
}

// ---- multi-block exclusive scan of g_rowcnt -> g_rowptr (+ dis fused) ----
__global__ void scan_block_kernel(int N) {
    __shared__ int wsum[32];
    int tid = threadIdx.x, lane = tid & 31, wid = tid >> 5;
    int i = blockIdx.x * 1024 + tid;
    if (i < N) {
        float d = g_deg[i];
        g_dis[i] = (d > 0.f) ? rsqrtf(d) : 0.f;
    }
    int v = (i < N) ? g_rowcnt[i] : 0;
    int s = v;
#pragma unroll
    for (int o = 1; o < 32; o <<= 1) {
        int u = __shfl_up_sync(0xffffffffu, s, o);
        if (lane >= o) s += u;
    }
    if (lane == 31) wsum[wid] = s;
    __syncthreads();
    if (tid < 32) {
        int s2 = wsum[tid];
#pragma unroll
        for (int o = 1; o < 32; o <<= 1) {
            int u = __shfl_up_sync(0xffffffffu, s2, o);
            if (tid >= o) s2 += u;
        }
        wsum[tid] = s2;
    }
    __syncthreads();
    int excl = (wid ? wsum[wid - 1] : 0) + (s - v);
    if (i < N) g_rowptr[i] = excl;
    if (tid == 1023) g_bsum[blockIdx.x] = wsum[31];
}

__global__ void scan_bsum_kernel(int nb) {
    __shared__ int ws[4];
    int tid = threadIdx.x, lane = tid & 31, wid = tid >> 5;
    int v = (tid < nb) ? g_bsum[tid] : 0;
    int s = v;
#pragma unroll
    for (int o = 1; o < 32; o <<= 1) {
        int u = __shfl_up_sync(0xffffffffu, s, o);
        if (lane >= o) s += u;
    }
    if (lane == 31) ws[wid] = s;
    __syncthreads();
    if (tid == 0) { int a = 0; for (int w = 0; w < 4; w++) { int t = ws[w]; ws[w] = a; a += t; } }
    __syncthreads();
    int excl = ws[wid] + (s - v);
    if (tid < nb) g_bsumoff[tid] = excl;
}

__global__ void scan_add_kernel(int N, int E) {
    int i = blockIdx.x * 1024 + threadIdx.x;
    if (i < N) {
        int r = g_rowptr[i] + g_bsumoff[blockIdx.x];
        g_rowptr[i] = r;
        g_cursor[i] = r;
    }
    if (blockIdx.x == 0 && threadIdx.x == 0) g_rowptr[N] = E;
}

__global__ void fill_kernel(const float* __restrict__ ew, int E) {
    int e = blockIdx.x * blockDim.x + threadIdx.x;
    if (e >= E) return;
    int s = g_src[e];
    int t = g_tgt[e];
    float wn = -g_dis[s] * ew[e] * g_dis[t];
    int pos = atomicAdd(&g_cursor[t], 1);
    g_epay[pos] = make_int2(s, __float_as_int(wn));
}

// Weff[l][kk][o]: kk<64 -> W0-W2 ; 64..127 -> W1 ; 128..191 -> 2*W2
__global__ void weff_kernel(const float* __restrict__ w) {
    int idx = blockIdx.x * blockDim.x + threadIdx.x;
    if (idx >= 4 * 192 * 64) return;
    int o  = idx & 63;
    int kk = (idx >> 6) % 192;
    int l  = idx / (192 * 64);
    const float* wl = w + (size_t)l * 3 * 4096;
    float v;
    if (kk < 64)       v = wl[kk * 64 + o] - wl[2 * 4096 + kk * 64 + o];
    else if (kk < 128) v = wl[4096 + (kk - 64) * 64 + o];
    else               v = 2.f * wl[2 * 4096 + (kk - 128) * 64 + o];
    g_weff[idx] = v;
}

// ---------------- warp-per-node CSR propagation (R9 proven version) ----------------
__global__ void prop_warp_kernel(const float* __restrict__ h, float* __restrict__ out, int n) {
    int node = (blockIdx.x * blockDim.x + threadIdx.x) >> 5;
    if (node >= n) return;
    int lane = threadIdx.x & 31;
    int beg = g_rowptr[node];
    int end = g_rowptr[node + 1];
    const float2* __restrict__ hp = reinterpret_cast<const float2*>(h);
    float ax = 0.f, ay = 0.f;
    for (int j0 = beg; j0 < end; j0 += 32) {
        int jj = j0 + lane;
        int2 p = (jj < end) ? g_epay[jj] : make_int2(0, 0);
        int cnt = end - j0;
        if (cnt > 32) cnt = 32;
#pragma unroll 4
        for (int k = 0; k < cnt; k++) {
            int s   = __shfl_sync(0xffffffffu, p.x, k);
            float w = __int_as_float(__shfl_sync(0xffffffffu, p.y, k));
            float2 v = hp[(size_t)s * 32 + lane];
            ax += w * v.x;
            ay += w * v.y;
        }
    }
    reinterpret_cast<float2*>(out)[(size_t)node * 32 + lane] = make_float2(ax, ay);
}

// ---------------- tensor-core GEMM: out = [p0|p1|p2] @ Weff + bias (3xTF32) ----------------
__device__ __forceinline__ uint32_t f2tf32(float x) {
    uint32_t r;
    asm("cvt.rna.tf32.f32 %0, %1;" : "=r"(r) : "f"(x));
    return r;
}

__device__ __forceinline__ void mma_tf32(float* d,
                                         uint32_t a0, uint32_t a1, uint32_t a2, uint32_t a3,
                                         uint32_t b0, uint32_t b1) {
    asm volatile("mma.sync.aligned.m16n8k8.row.col.f32.tf32.tf32.f32 "
                 "{%0,%1,%2,%3}, {%4,%5,%6,%7}, {%8,%9}, {%0,%1,%2,%3};"
                 : "+f"(d[0]), "+f"(d[1]), "+f"(d[2]), "+f"(d[3])
                 : "r"(a0), "r"(a1), "r"(a2), "r"(a3), "r"(b0), "r"(b1));
}

// BM=128, BN=64, K=192 (6 chunks of 32). 8 warps, 32x32 warp tiles.
// SMEM strides 136/72 (=8 mod 32) -> conflict-free LDS for frag patterns.
__global__ void __launch_bounds__(256, 2)
gemm_tc_kernel(const float* __restrict__ p0, const float* __restrict__ p1,
               const float* __restrict__ p2, const float* __restrict__ W,
               const float* __restrict__ bias, float* __restrict__ out, int N) {
    __shared__ float As[32][136];     // [k][row]
    __shared__ float Whi[32][72];     // [k][n]
    __shared__ float Wlo[32][72];
    int tid = threadIdx.x;
    int lane = tid & 31;
    int wid = tid >> 5;               // 0..7
    int warp_m = wid >> 1;            // 0..3
    int warp_n = wid & 1;             // 0..1
    int gid = lane >> 2;              // 0..7
    int tig = lane & 3;               // 0..3
    int m0 = blockIdx.x * 128;

    float acc[2][4][4];
#pragma unroll
    for (int mf = 0; mf < 2; mf++)
#pragma unroll
        for (int nf = 0; nf < 4; nf++)
#pragma unroll
            for (int q = 0; q < 4; q++) acc[mf][nf][q] = 0.f;

    const float* parts[3] = {p0, p1, p2};

#pragma unroll 1
    for (int c = 0; c < 6; c++) {
        const float* P = parts[c >> 1];
        int kbase = (c & 1) * 32;      // column offset within the part
        // stage A chunk: 128 rows x 32 k
#pragma unroll
        for (int i = 0; i < 4; i++) {
            int idx = i * 256 + tid;
            int row = idx & 127;
            int kq = idx >> 7;         // 0..7
            int grow = m0 + row;
            float4 v = make_float4(0.f, 0.f, 0.f, 0.f);
            if (grow < N)
                v = *reinterpret_cast<const float4*>(P + (size_t)grow * 64 + kbase + kq * 4);
            As[kq * 4 + 0][row] = v.x;
            As[kq * 4 + 1][row] = v.y;
            As[kq * 4 + 2][row] = v.z;
            As[kq * 4 + 3][row] = v.w;
        }
        // stage W chunk (32 k-rows x 64 n) split into tf32 hi/lo
#pragma unroll
        for (int i = 0; i < 8; i++) {
            int idx = i * 256 + tid;
            int k = idx >> 6;          // 0..31
            int n = idx & 63;
            float w = W[(size_t)(c * 32 + k) * 64 + n];
            uint32_t hb = f2tf32(w);
            float lof = w - __uint_as_float(hb);
            Whi[k][n] = __uint_as_float(hb);
            Wlo[k][n] = __uint_as_float(f2tf32(lof));
        }
        __syncthreads();

#pragma unroll
        for (int ks = 0; ks < 4; ks++) {
            int k0 = ks * 8;
            // B fragments (hi and lo)
            uint32_t bh[4][2], bl[4][2];
#pragma unroll
            for (int nf = 0; nf < 4; nf++) {
                int col = warp_n * 32 + nf * 8 + gid;
                bh[nf][0] = __float_as_uint(Whi[k0 + tig][col]);
                bh[nf][1] = __float_as_uint(Whi[k0 + tig + 4][col]);
                bl[nf][0] = __float_as_uint(Wlo[k0 + tig][col]);
                bl[nf][1] = __float_as_uint(Wlo[k0 + tig + 4][col]);
            }
            // A fragments, split hi/lo in registers
            uint32_t ah[2][4], al[2][4];
#pragma unroll
            for (int mf = 0; mf < 2; mf++) {
                int rb = warp_m * 32 + mf * 16;
                float a0 = As[k0 + tig][rb + gid];
                float a1 = As[k0 + tig][rb + gid + 8];
                float a2 = As[k0 + tig + 4][rb + gid];
                float a3 = As[k0 + tig + 4][rb + gid + 8];
                // PTX m16n8k8 A frag: a0=A[g][t], a1=A[g+8][t], a2=A[g][t+4], a3=A[g+8][t+4]
                float av[4] = {a0, a1, a2, a3};
#pragma unroll
                for (int q = 0; q < 4; q++) {
                    uint32_t hb = f2tf32(av[q]);
                    ah[mf][q] = hb;
                    al[mf][q] = f2tf32(av[q] - __uint_as_float(hb));
                }
            }
            // 3xTF32 products
#pragma unroll
            for (int mf = 0; mf < 2; mf++)
#pragma unroll
                for (int nf = 0; nf < 4; nf++) {
                    mma_tf32(acc[mf][nf], ah[mf][0], ah[mf][1], ah[mf][2], ah[mf][3],
                             bh[nf][0], bh[nf][1]);
                    mma_tf32(acc[mf][nf], ah[mf][0], ah[mf][1], ah[mf][2], ah[mf][3],
                             bl[nf][0], bl[nf][1]);
                    mma_tf32(acc[mf][nf], al[mf][0], al[mf][1], al[mf][2], al[mf][3],
                             bh[nf][0], bh[nf][1]);
                }
        }
        __syncthreads();
    }

    // epilogue: bias + store (C frag: c0=C[g][2t], c1=C[g][2t+1], c2=C[g+8][2t], c3=C[g+8][2t+1])
#pragma unroll
    for (int mf = 0; mf < 2; mf++) {
#pragma unroll
        for (int nf = 0; nf < 4; nf++) {
            int col = warp_n * 32 + nf * 8 + 2 * tig;
            float b0 = bias[col], b1 = bias[col + 1];
            int row0 = m0 + warp_m * 32 + mf * 16 + gid;
            if (row0 < N) {
                float2 o = make_float2(acc[mf][nf][0] + b0, acc[mf][nf][1] + b1);
                *reinterpret_cast<float2*>(out + (size_t)row0 * 64 + col) = o;
            }
            int row1 = row0 + 8;
            if (row1 < N) {
                float2 o = make_float2(acc[mf][nf][2] + b0, acc[mf][nf][3] + b1);
                *reinterpret_cast<float2*>(out + (size_t)row1 * 64 + col) = o;
            }
        }
    }
}

// ---------------- readout MLP (64->32 relu ->1) + scatter mean ----------------
__global__ void readout_kernel(const float* __restrict__ y, const int* __restrict__ batch,
                               const float* __restrict__ wr1, const float* __restrict__ br1,
                               const float* __restrict__ wr2, const float* __restrict__ br2,
                               int n, int G) {
    __shared__ float Wsm[64 * 32];
    __shared__ float w2sm[32];
    __shared__ float b1sm[32];
    for (int i = threadIdx.x; i < 64 * 32; i += blockDim.x) Wsm[i] = wr1[i];
    if (threadIdx.x < 32) {
        w2sm[threadIdx.x] = wr2[threadIdx.x];
        b1sm[threadIdx.x] = br1[threadIdx.x];
    }
    __syncthreads();
    float b2 = br2[0];
    int lane = threadIdx.x & 31;
    int warp = (blockIdx.x * blockDim.x + threadIdx.x) >> 5;
    int nwarps = (gridDim.x * blockDim.x) >> 5;
    for (int node = warp; node < n; node += nwarps) {
        float yv0 = y[(size_t)node * 64 + lane];
        float yv1 = y[(size_t)node * 64 + 32 + lane];
        float acc = b1sm[lane];
#pragma unroll
        for (int k = 0; k < 32; k++)
            acc += __shfl_sync(0xffffffffu, yv0, k) * Wsm[k * 32 + lane];
#pragma unroll
        for (int k = 0; k < 32; k++)
            acc += __shfl_sync(0xffffffffu, yv1, k) * Wsm[(32 + k) * 32 + lane];
        acc = fmaxf(acc, 0.f);
        float r = acc * w2sm[lane];
#pragma unroll
        for (int off = 16; off; off >>= 1)
            r += __shfl_xor_sync(0xffffffffu, r, off);
        if (lane == 0) {
            int g = batch[node];
            if ((unsigned)g < (unsigned)G) {
                atomicAdd(&g_sums[g], r + b2);
                atomicAdd(&g_cnt[g], 1.f);
            }
        }
    }
}

__global__ void finalize_kernel(float* __restrict__ out, int G) {
    int g = threadIdx.x;
    if (g < G) out[g] = g_sums[g] / fmaxf(g_cnt[g], 1.f);
}

// ---------------- host ----------------
extern "C" void kernel_launch(void* const* d_in, const int* in_sizes, int n_in,
                              void* d_out, int out_size) {
    const float* x        = (const float*)d_in[0];
    const int*   ei       = (const int*)d_in[1];     // int32 (JAX x64 disabled)
    const float* ew       = (const float*)d_in[2];
    const int*   batch    = (const int*)d_in[3];     // int32
    const float* w_layers = (const float*)d_in[4];
    const float* b_layers = (const float*)d_in[5];
    const float* wr1      = (const float*)d_in[6];
    const float* br1      = (const float*)d_in[7];
    const float* wr2      = (const float*)d_in[8];
    const float* br2      = (const float*)d_in[9];

    int N = in_sizes[0] / HDIM;
    int E = in_sizes[1] / 2;
    int G = out_size;

    float *bufA, *bufB, *tx1, *tmp, *weff;
    cudaGetSymbolAddress((void**)&bufA, g_bufA);
    cudaGetSymbolAddress((void**)&bufB, g_bufB);
    cudaGetSymbolAddress((void**)&tx1,  g_tx1);
    cudaGetSymbolAddress((void**)&tmp,  g_tmp);
    cudaGetSymbolAddress((void**)&weff, g_weff);

    const int TPB = 256;
    int nb = (N + 1023) / 1024;

    // preprocessing: degrees + CSR by target
    init_counts_kernel<<<(N + TPB - 1) / TPB, TPB>>>(N);
    edge_prep_kernel<<<(E + TPB - 1) / TPB, TPB>>>(ei, ew, E, N);
    scan_block_kernel<<<nb, 1024>>>(N);
    scan_bsum_kernel<<<1, 128>>>(nb);
    scan_add_kernel<<<nb, 1024>>>(N, E);
    fill_kernel<<<(E + TPB - 1) / TPB, TPB>>>(ew, E);
    weff_kernel<<<(4 * 192 * 64 + TPB - 1) / TPB, TPB>>>(w_layers);

    int pgrid = (int)(((long long)N * 32 + TPB - 1) / TPB);
    int ggrid = (N + 127) / 128;

    const float* ycur = x;
    float* bufs[2] = {bufA, bufB};
    for (int l = 0; l < 4; l++) {
        prop_warp_kernel<<<pgrid, TPB>>>(ycur, tx1, N);
        prop_warp_kernel<<<pgrid, TPB>>>(tx1, tmp, N);
        gemm_tc_kernel<<<ggrid, TPB>>>(ycur, tx1, tmp,
                                       weff + (size_t)l * 192 * 64,
                                       b_layers + (size_t)l * 64,
                                       bufs[l & 1], N);
        ycur = bufs[l & 1];
    }

    // readout + pooling
    zero_pool_kernel<<<1, 128>>>();
    readout_kernel<<<256, TPB>>>(ycur, batch, wr1, br1, wr2, br2, N, G);
    finalize_kernel<<<1, 64>>>((float*)d_out, G);
}

// round 13
// speedup vs baseline: 1.3178x; 1.0009x over previous
#include <cuda_runtime.h>
#include <cstdint>

// ---------------- static scratch (device globals: allocation-free) ----------------
#define NMAX 100000
#define EMAX 1600000
#define HDIM 64

__device__ float g_deg[NMAX];
__device__ float g_dis[NMAX];
__device__ int   g_src[EMAX];
__device__ int   g_tgt[EMAX];
__device__ int   g_rowcnt[NMAX];
__device__ int   g_rowptr[NMAX + 1];
__device__ int   g_cursor[NMAX];
__device__ int   g_bsum[128];
__device__ int   g_bsumoff[128];
__device__ int2  g_epay[EMAX];          // {src, bits(wn)} grouped by tgt
__device__ float g_bufA[(size_t)NMAX * HDIM];
__device__ float g_bufB[(size_t)NMAX * HDIM];
__device__ float g_tx1[(size_t)NMAX * HDIM];
__device__ float g_tmp[(size_t)NMAX * HDIM];
__device__ float g_weff[4 * 192 * 64];
__device__ float g_sums[64];
__device__ float g_cnt[64];

// ---------------- utility ----------------
__global__ void init_counts_kernel(int n) {
    int i = blockIdx.x * blockDim.x + threadIdx.x;
    if (i < n) { g_deg[i] = 0.f; g_rowcnt[i] = 0; }
}

__global__ void zero_pool_kernel() {
    int i = threadIdx.x;
    if (i < 64) g_sums[i] = 0.f;
    else if (i < 128) g_cnt[i - 64] = 0.f;
}

// ---------------- preprocessing ----------------
__global__ void edge_prep_kernel(const int* __restrict__ ei,
                                 const float* __restrict__ ew, int E, int N) {
    int e = blockIdx.x * blockDim.x + threadIdx.x;
    if (e >= E) return;
    int s = ei[e];
    int t = ei[(size_t)E + e];
    if ((unsigned)s >= (unsigned)N) s = 0;
    if ((unsigned)t >= (unsigned)N) t = 0;
    g_src[e] = s;
    g_tgt[e] = t;
    atomicAdd(&g_deg[s], ew[e]);
    atomicAdd(&g_rowcnt[t], 1);
}

// ---- multi-block exclusive scan of g_rowcnt -> g_rowptr (+ dis fused) ----
__global__ void scan_block_kernel(int N) {
    __shared__ int wsum[32];
    int tid = threadIdx.x, lane = tid & 31, wid = tid >> 5;
    int i = blockIdx.x * 1024 + tid;
    if (i < N) {
        float d = g_deg[i];
        g_dis[i] = (d > 0.f) ? rsqrtf(d) : 0.f;
    }
    int v = (i < N) ? g_rowcnt[i] : 0;
    int s = v;
#pragma unroll
    for (int o = 1; o < 32; o <<= 1) {
        int u = __shfl_up_sync(0xffffffffu, s, o);
        if (lane >= o) s += u;
    }
    if (lane == 31) wsum[wid] = s;
    __syncthreads();
    if (tid < 32) {
        int s2 = wsum[tid];
#pragma unroll
        for (int o = 1; o < 32; o <<= 1) {
            int u = __shfl_up_sync(0xffffffffu, s2, o);
            if (tid >= o) s2 += u;
        }
        wsum[tid] = s2;
    }
    __syncthreads();
    int excl = (wid ? wsum[wid - 1] : 0) + (s - v);
    if (i < N) g_rowptr[i] = excl;
    if (tid == 1023) g_bsum[blockIdx.x] = wsum[31];
}

__global__ void scan_bsum_kernel(int nb) {
    __shared__ int ws[4];
    int tid = threadIdx.x, lane = tid & 31, wid = tid >> 5;
    int v = (tid < nb) ? g_bsum[tid] : 0;
    int s = v;
#pragma unroll
    for (int o = 1; o < 32; o <<= 1) {
        int u = __shfl_up_sync(0xffffffffu, s, o);
        if (lane >= o) s += u;
    }
    if (lane == 31) ws[wid] = s;
    __syncthreads();
    if (tid == 0) { int a = 0; for (int w = 0; w < 4; w++) { int t = ws[w]; ws[w] = a; a += t; } }
    __syncthreads();
    int excl = ws[wid] + (s - v);
    if (tid < nb) g_bsumoff[tid] = excl;
}

__global__ void scan_add_kernel(int N, int E) {
    int i = blockIdx.x * 1024 + threadIdx.x;
    if (i < N) {
        int r = g_rowptr[i] + g_bsumoff[blockIdx.x];
        g_rowptr[i] = r;
        g_cursor[i] = r;
    }
    if (blockIdx.x == 0 && threadIdx.x == 0) g_rowptr[N] = E;
}

__global__ void fill_kernel(const float* __restrict__ ew, int E) {
    int e = blockIdx.x * blockDim.x + threadIdx.x;
    if (e >= E) return;
    int s = g_src[e];
    int t = g_tgt[e];
    float wn = -g_dis[s] * ew[e] * g_dis[t];
    int pos = atomicAdd(&g_cursor[t], 1);
    g_epay[pos] = make_int2(s, __float_as_int(wn));
}

// Weff[l][kk][o]: kk<64 -> W0-W2 ; 64..127 -> W1 ; 128..191 -> 2*W2
__global__ void weff_kernel(const float* __restrict__ w) {
    int idx = blockIdx.x * blockDim.x + threadIdx.x;
    if (idx >= 4 * 192 * 64) return;
    int o  = idx & 63;
    int kk = (idx >> 6) % 192;
    int l  = idx / (192 * 64);
    const float* wl = w + (size_t)l * 3 * 4096;
    float v;
    if (kk < 64)       v = wl[kk * 64 + o] - wl[2 * 4096 + kk * 64 + o];
    else if (kk < 128) v = wl[4096 + (kk - 64) * 64 + o];
    else               v = 2.f * wl[2 * 4096 + (kk - 128) * 64 + o];
    g_weff[idx] = v;
}

// ---------------- warp-per-node CSR propagation (R9 proven version) ----------------
__global__ void prop_warp_kernel(const float* __restrict__ h, float* __restrict__ out, int n) {
    int node = (blockIdx.x * blockDim.x + threadIdx.x) >> 5;
    if (node >= n) return;
    int lane = threadIdx.x & 31;
    int beg = g_rowptr[node];
    int end = g_rowptr[node + 1];
    const float2* __restrict__ hp = reinterpret_cast<const float2*>(h);
    float ax = 0.f, ay = 0.f;
    for (int j0 = beg; j0 < end; j0 += 32) {
        int jj = j0 + lane;
        int2 p = (jj < end) ? g_epay[jj] : make_int2(0, 0);
        int cnt = end - j0;
        if (cnt > 32) cnt = 32;
#pragma unroll 4
        for (int k = 0; k < cnt; k++) {
            int s   = __shfl_sync(0xffffffffu, p.x, k);
            float w = __int_as_float(__shfl_sync(0xffffffffu, p.y, k));
            float2 v = hp[(size_t)s * 32 + lane];
            ax += w * v.x;
            ay += w * v.y;
        }
    }
    reinterpret_cast<float2*>(out)[(size_t)node * 32 + lane] = make_float2(ax, ay);
}

// ---------------- tensor-core GEMM: out = [p0|p1|p2] @ Weff + bias (3xTF32) ----------------
__device__ __forceinline__ uint32_t f2tf32(float x) {
    uint32_t r;
    asm("cvt.rna.tf32.f32 %0, %1;" : "=r"(r) : "f"(x));
    return r;
}

__device__ __forceinline__ void mma_tf32(float* d,
                                         uint32_t a0, uint32_t a1, uint32_t a2, uint32_t a3,
                                         uint32_t b0, uint32_t b1) {
    asm volatile("mma.sync.aligned.m16n8k8.row.col.f32.tf32.tf32.f32 "
                 "{%0,%1,%2,%3}, {%4,%5,%6,%7}, {%8,%9}, {%0,%1,%2,%3};"
                 : "+f"(d[0]), "+f"(d[1]), "+f"(d[2]), "+f"(d[3])
                 : "r"(a0), "r"(a1), "r"(a2), "r"(a3), "r"(b0), "r"(b1));
}

// BM=128, BN=64, K=192 (6 chunks of 32). 8 warps, 32x32 warp tiles.
// SMEM strides 136/72 (=8 mod 32) -> conflict-free LDS for frag patterns.
__global__ void __launch_bounds__(256, 2)
gemm_tc_kernel(const float* __restrict__ p0, const float* __restrict__ p1,
               const float* __restrict__ p2, const float* __restrict__ W,
               const float* __restrict__ bias, float* __restrict__ out, int N) {
    __shared__ float As[32][136];     // [k][row]
    __shared__ float Whi[32][72];     // [k][n]
    __shared__ float Wlo[32][72];
    int tid = threadIdx.x;
    int lane = tid & 31;
    int wid = tid >> 5;               // 0..7
    int warp_m = wid >> 1;            // 0..3
    int warp_n = wid & 1;             // 0..1
    int gid = lane >> 2;              // 0..7
    int tig = lane & 3;               // 0..3
    int m0 = blockIdx.x * 128;

    float acc[2][4][4];
#pragma unroll
    for (int mf = 0; mf < 2; mf++)
#pragma unroll
        for (int nf = 0; nf < 4; nf++)
#pragma unroll
            for (int q = 0; q < 4; q++) acc[mf][nf][q] = 0.f;

    const float* parts[3] = {p0, p1, p2};

#pragma unroll 1
    for (int c = 0; c < 6; c++) {
        const float* P = parts[c >> 1];
        int kbase = (c & 1) * 32;      // column offset within the part
        // stage A chunk: 128 rows x 32 k
#pragma unroll
        for (int i = 0; i < 4; i++) {
            int idx = i * 256 + tid;
            int row = idx & 127;
            int kq = idx >> 7;         // 0..7
            int grow = m0 + row;
            float4 v = make_float4(0.f, 0.f, 0.f, 0.f);
            if (grow < N)
                v = *reinterpret_cast<const float4*>(P + (size_t)grow * 64 + kbase + kq * 4);
            As[kq * 4 + 0][row] = v.x;
            As[kq * 4 + 1][row] = v.y;
            As[kq * 4 + 2][row] = v.z;
            As[kq * 4 + 3][row] = v.w;
        }
        // stage W chunk (32 k-rows x 64 n) split into tf32 hi/lo
#pragma unroll
        for (int i = 0; i < 8; i++) {
            int idx = i * 256 + tid;
            int k = idx >> 6;          // 0..31
            int n = idx & 63;
            float w = W[(size_t)(c * 32 + k) * 64 + n];
            uint32_t hb = f2tf32(w);
            float lof = w - __uint_as_float(hb);
            Whi[k][n] = __uint_as_float(hb);
            Wlo[k][n] = __uint_as_float(f2tf32(lof));
        }
        __syncthreads();

#pragma unroll
        for (int ks = 0; ks < 4; ks++) {
            int k0 = ks * 8;
            // B fragments (hi and lo)
            uint32_t bh[4][2], bl[4][2];
#pragma unroll
            for (int nf = 0; nf < 4; nf++) {
                int col = warp_n * 32 + nf * 8 + gid;
                bh[nf][0] = __float_as_uint(Whi[k0 + tig][col]);
                bh[nf][1] = __float_as_uint(Whi[k0 + tig + 4][col]);
                bl[nf][0] = __float_as_uint(Wlo[k0 + tig][col]);
                bl[nf][1] = __float_as_uint(Wlo[k0 + tig + 4][col]);
            }
            // A fragments, split hi/lo in registers
            uint32_t ah[2][4], al[2][4];
#pragma unroll
            for (int mf = 0; mf < 2; mf++) {
                int rb = warp_m * 32 + mf * 16;
                float a0 = As[k0 + tig][rb + gid];
                float a1 = As[k0 + tig][rb + gid + 8];
                float a2 = As[k0 + tig + 4][rb + gid];
                float a3 = As[k0 + tig + 4][rb + gid + 8];
                // PTX m16n8k8 A frag: a0=A[g][t], a1=A[g+8][t], a2=A[g][t+4], a3=A[g+8][t+4]
                float av[4] = {a0, a1, a2, a3};
#pragma unroll
                for (int q = 0; q < 4; q++) {
                    uint32_t hb = f2tf32(av[q]);
                    ah[mf][q] = hb;
                    al[mf][q] = f2tf32(av[q] - __uint_as_float(hb));
                }
            }
            // 3xTF32 products
#pragma unroll
            for (int mf = 0; mf < 2; mf++)
#pragma unroll
                for (int nf = 0; nf < 4; nf++) {
                    mma_tf32(acc[mf][nf], ah[mf][0], ah[mf][1], ah[mf][2], ah[mf][3],
                             bh[nf][0], bh[nf][1]);
                    mma_tf32(acc[mf][nf], ah[mf][0], ah[mf][1], ah[mf][2], ah[mf][3],
                             bl[nf][0], bl[nf][1]);
                    mma_tf32(acc[mf][nf], al[mf][0], al[mf][1], al[mf][2], al[mf][3],
                             bh[nf][0], bh[nf][1]);
                }
        }
        __syncthreads();
    }

    // epilogue: bias + store (C frag: c0=C[g][2t], c1=C[g][2t+1], c2=C[g+8][2t], c3=C[g+8][2t+1])
#pragma unroll
    for (int mf = 0; mf < 2; mf++) {
#pragma unroll
        for (int nf = 0; nf < 4; nf++) {
            int col = warp_n * 32 + nf * 8 + 2 * tig;
            float b0 = bias[col], b1 = bias[col + 1];
            int row0 = m0 + warp_m * 32 + mf * 16 + gid;
            if (row0 < N) {
                float2 o = make_float2(acc[mf][nf][0] + b0, acc[mf][nf][1] + b1);
                *reinterpret_cast<float2*>(out + (size_t)row0 * 64 + col) = o;
            }
            int row1 = row0 + 8;
            if (row1 < N) {
                float2 o = make_float2(acc[mf][nf][2] + b0, acc[mf][nf][3] + b1);
                *reinterpret_cast<float2*>(out + (size_t)row1 * 64 + col) = o;
            }
        }
    }
}

// ---------------- readout MLP (64->32 relu ->1) + scatter mean ----------------
__global__ void readout_kernel(const float* __restrict__ y, const int* __restrict__ batch,
                               const float* __restrict__ wr1, const float* __restrict__ br1,
                               const float* __restrict__ wr2, const float* __restrict__ br2,
                               int n, int G) {
    __shared__ float Wsm[64 * 32];
    __shared__ float w2sm[32];
    __shared__ float b1sm[32];
    for (int i = threadIdx.x; i < 64 * 32; i += blockDim.x) Wsm[i] = wr1[i];
    if (threadIdx.x < 32) {
        w2sm[threadIdx.x] = wr2[threadIdx.x];
        b1sm[threadIdx.x] = br1[threadIdx.x];
    }
    __syncthreads();
    float b2 = br2[0];
    int lane = threadIdx.x & 31;
    int warp = (blockIdx.x * blockDim.x + threadIdx.x) >> 5;
    int nwarps = (gridDim.x * blockDim.x) >> 5;
    for (int node = warp; node < n; node += nwarps) {
        float yv0 = y[(size_t)node * 64 + lane];
        float yv1 = y[(size_t)node * 64 + 32 + lane];
        float acc = b1sm[lane];
#pragma unroll
        for (int k = 0; k < 32; k++)
            acc += __shfl_sync(0xffffffffu, yv0, k) * Wsm[k * 32 + lane];
#pragma unroll
        for (int k = 0; k < 32; k++)
            acc += __shfl_sync(0xffffffffu, yv1, k) * Wsm[(32 + k) * 32 + lane];
        acc = fmaxf(acc, 0.f);
        float r = acc * w2sm[lane];
#pragma unroll
        for (int off = 16; off; off >>= 1)
            r += __shfl_xor_sync(0xffffffffu, r, off);
        if (lane == 0) {
            int g = batch[node];
            if ((unsigned)g < (unsigned)G) {
                atomicAdd(&g_sums[g], r + b2);
                atomicAdd(&g_cnt[g], 1.f);
            }
        }
    }
}

__global__ void finalize_kernel(float* __restrict__ out, int G) {
    int g = threadIdx.x;
    if (g < G) out[g] = g_sums[g] / fmaxf(g_cnt[g], 1.f);
}

// ---------------- host ----------------
extern "C" void kernel_launch(void* const* d_in, const int* in_sizes, int n_in,
                              void* d_out, int out_size) {
    const float* x        = (const float*)d_in[0];
    const int*   ei       = (const int*)d_in[1];     // int32 (JAX x64 disabled)
    const float* ew       = (const float*)d_in[2];
    const int*   batch    = (const int*)d_in[3];     // int32
    const float* w_layers = (const float*)d_in[4];
    const float* b_layers = (const float*)d_in[5];
    const float* wr1      = (const float*)d_in[6];
    const float* br1      = (const float*)d_in[7];
    const float* wr2      = (const float*)d_in[8];
    const float* br2      = (const float*)d_in[9];

    int N = in_sizes[0] / HDIM;
    int E = in_sizes[1] / 2;
    int G = out_size;

    float *bufA, *bufB, *tx1, *tmp, *weff;
    cudaGetSymbolAddress((void**)&bufA, g_bufA);
    cudaGetSymbolAddress((void**)&bufB, g_bufB);
    cudaGetSymbolAddress((void**)&tx1,  g_tx1);
    cudaGetSymbolAddress((void**)&tmp,  g_tmp);
    cudaGetSymbolAddress((void**)&weff, g_weff);

    const int TPB = 256;
    int nb = (N + 1023) / 1024;

    // preprocessing: degrees + CSR by target
    init_counts_kernel<<<(N + TPB - 1) / TPB, TPB>>>(N);
    edge_prep_kernel<<<(E + TPB - 1) / TPB, TPB>>>(ei, ew, E, N);
    scan_block_kernel<<<nb, 1024>>>(N);
    scan_bsum_kernel<<<1, 128>>>(nb);
    scan_add_kernel<<<nb, 1024>>>(N, E);
    fill_kernel<<<(E + TPB - 1) / TPB, TPB>>>(ew, E);
    weff_kernel<<<(4 * 192 * 64 + TPB - 1) / TPB, TPB>>>(w_layers);

    int pgrid = (int)(((long long)N * 32 + TPB - 1) / TPB);
    int ggrid = (N + 127) / 128;

    const float* ycur = x;
    float* bufs[2] = {bufA, bufB};
    for (int l = 0; l < 4; l++) {
        prop_warp_kernel<<<pgrid, TPB>>>(ycur, tx1, N);
        prop_warp_kernel<<<pgrid, TPB>>>(tx1, tmp, N);
        gemm_tc_kernel<<<ggrid, TPB>>>(ycur, tx1, tmp,
                                       weff + (size_t)l * 192 * 64,
                                       b_layers + (size_t)l * 64,
                                       bufs[l & 1], N);
        ycur = bufs[l & 1];
    }

    // readout + pooling
    zero_pool_kernel<<<1, 128>>>();
    readout_kernel<<<256, TPB>>>(ycur, batch, wr1, br1, wr2, br2, N, G);
    finalize_kernel<<<1, 64>>>((float*)d_out, G);
}